// round 1
// baseline (speedup 1.0000x reference)
#include <cuda_runtime.h>
#include <math.h>

#define T_SEQ   2048
#define BATCH   2
#define DM      512
#define NROWS   (BATCH * T_SEQ)   // 4096
#define QKV_N   (3 * DM)          // 1536
#define WIN     32
#define WW      (2 * WIN - 1)     // 63

// Scratch (allocation-free rule: __device__ globals)
__device__ float g_qkv[NROWS * QKV_N];   // [4096, 1536] : q | k | v
__device__ float g_att[NROWS * DM];      // [4096, 512]

// ---------------------------------------------------------------------------
// C[M,N] = A[M,K] @ B[N,K]^T + bias[N]   (both operands K-major / row-major)
// Classic 128x128x8 SGEMM, 256 threads, 8x8 per-thread microtile.
// Requires M%128==0, N%128==0, K%8==0 (true for both GEMMs here).
// ---------------------------------------------------------------------------
__global__ __launch_bounds__(256) void sgemm_nt_bias(
    int M, int N, int K,
    const float* __restrict__ A,
    const float* __restrict__ B,
    const float* __restrict__ bias,
    float* __restrict__ C)
{
    const int BM = 128, BN = 128, BK = 8;
    __shared__ float As[BK][BM];
    __shared__ float Bs[BK][BN];

    const int tid = threadIdx.x;
    const int tx  = tid & 15;        // 0..15 -> N direction
    const int ty  = tid >> 4;        // 0..15 -> M direction
    const int m0  = blockIdx.y * BM;
    const int n0  = blockIdx.x * BN;

    const int lrow = tid >> 1;       // 0..127
    const int lk   = (tid & 1) * 4;  // 0 or 4

    float acc[8][8];
#pragma unroll
    for (int i = 0; i < 8; i++)
#pragma unroll
        for (int j = 0; j < 8; j++) acc[i][j] = 0.0f;

    const float* Ap = A + (size_t)(m0 + lrow) * K + lk;
    const float* Bp = B + (size_t)(n0 + lrow) * K + lk;

    for (int k0 = 0; k0 < K; k0 += BK) {
        float4 av = *reinterpret_cast<const float4*>(Ap + k0);
        float4 bv = *reinterpret_cast<const float4*>(Bp + k0);
        As[lk + 0][lrow] = av.x;
        As[lk + 1][lrow] = av.y;
        As[lk + 2][lrow] = av.z;
        As[lk + 3][lrow] = av.w;
        Bs[lk + 0][lrow] = bv.x;
        Bs[lk + 1][lrow] = bv.y;
        Bs[lk + 2][lrow] = bv.z;
        Bs[lk + 3][lrow] = bv.w;
        __syncthreads();

#pragma unroll
        for (int k = 0; k < BK; k++) {
            float a[8], b[8];
#pragma unroll
            for (int i = 0; i < 8; i++) a[i] = As[k][ty * 8 + i];
#pragma unroll
            for (int j = 0; j < 8; j++) b[j] = Bs[k][tx * 8 + j];
#pragma unroll
            for (int i = 0; i < 8; i++)
#pragma unroll
                for (int j = 0; j < 8; j++)
                    acc[i][j] = fmaf(a[i], b[j], acc[i][j]);
        }
        __syncthreads();
    }

#pragma unroll
    for (int i = 0; i < 8; i++) {
        const int row = m0 + ty * 8 + i;
        float* crow = C + (size_t)row * N + n0 + tx * 8;
        const float* brow = bias + n0 + tx * 8;
#pragma unroll
        for (int j = 0; j < 8; j++)
            crow[j] = acc[i][j] + brow[j];
    }
}

// ---------------------------------------------------------------------------
// Local windowed attention. One warp handles 2 consecutive sequence rows.
// Lane l owns channels {l, l+32, ..., l+480} (16 per lane).
// Scores for row dt live 2-per-lane: lane w holds w, lane w-32 holds w (w>=32).
// k/v rows are re-read per warp but the whole qkv scratch (25 MB) is
// L2-resident, so this is L2-bandwidth bound, not DRAM bound.
// ---------------------------------------------------------------------------
__global__ __launch_bounds__(256) void local_attn(
    const float* __restrict__ qkv, float* __restrict__ out)
{
    const int lane = threadIdx.x & 31;
    const int wg   = (blockIdx.x * blockDim.x + threadIdx.x) >> 5;
    const int m0   = wg * 2;                 // two rows: m0, m0+1 (same batch)
    const int t0   = m0 & (T_SEQ - 1);

    const float NEG = -1e30f;
    const float inv_scale = 1.0f / 22.62741699796952f;  // 1/sqrt(512)

    // load q for both rows
    float q[2][16];
#pragma unroll
    for (int dt = 0; dt < 2; dt++) {
        const float* qp = qkv + (size_t)(m0 + dt) * QKV_N + lane;
#pragma unroll
        for (int j = 0; j < 16; j++) q[dt][j] = qp[32 * j];
    }

    float s[2][2] = {{NEG, NEG}, {NEG, NEG}};

    // ---- scores ----
    for (int d = -(WIN - 1); d <= WIN; d++) {      // union window of both rows
        const int rt = t0 + d;
        if (rt < 0 || rt >= T_SEQ) continue;
        const float* kp = qkv + (size_t)(m0 + d) * QKV_N + DM + lane;
        float kr[16];
#pragma unroll
        for (int j = 0; j < 16; j++) kr[j] = kp[32 * j];

#pragma unroll
        for (int dt = 0; dt < 2; dt++) {
            const int w = d - dt + (WIN - 1);      // 0..62 valid
            if (w < 0 || w >= WW) continue;
            float dot = 0.0f;
#pragma unroll
            for (int j = 0; j < 16; j++) dot = fmaf(q[dt][j], kr[j], dot);
#pragma unroll
            for (int o = 16; o > 0; o >>= 1)
                dot += __shfl_xor_sync(0xffffffffu, dot, o);
            if (lane == (w & 31)) s[dt][w >> 5] = dot;
        }
    }

    // ---- softmax (per row) ----
#pragma unroll
    for (int dt = 0; dt < 2; dt++) {
        float s0 = s[dt][0] * inv_scale;
        float s1 = s[dt][1] * inv_scale;
        float mx = fmaxf(s0, s1);
#pragma unroll
        for (int o = 16; o > 0; o >>= 1)
            mx = fmaxf(mx, __shfl_xor_sync(0xffffffffu, mx, o));
        float e0 = __expf(s0 - mx);
        float e1 = __expf(s1 - mx);
        float sum = e0 + e1;
#pragma unroll
        for (int o = 16; o > 0; o >>= 1)
            sum += __shfl_xor_sync(0xffffffffu, sum, o);
        float inv = 1.0f / sum;
        s[dt][0] = e0 * inv;
        s[dt][1] = e1 * inv;
    }

    // ---- output: out = p @ v_win ----
    float o[2][16];
#pragma unroll
    for (int dt = 0; dt < 2; dt++)
#pragma unroll
        for (int j = 0; j < 16; j++) o[dt][j] = 0.0f;

    for (int d = -(WIN - 1); d <= WIN; d++) {
        const int rt = t0 + d;
        if (rt < 0 || rt >= T_SEQ) continue;
        const float* vp = qkv + (size_t)(m0 + d) * QKV_N + 2 * DM + lane;
        float vr[16];
#pragma unroll
        for (int j = 0; j < 16; j++) vr[j] = vp[32 * j];

#pragma unroll
        for (int dt = 0; dt < 2; dt++) {
            const int w = d - dt + (WIN - 1);
            if (w < 0 || w >= WW) continue;
            const float p = __shfl_sync(0xffffffffu, s[dt][w >> 5], w & 31);
#pragma unroll
            for (int j = 0; j < 16; j++) o[dt][j] = fmaf(p, vr[j], o[dt][j]);
        }
    }

#pragma unroll
    for (int dt = 0; dt < 2; dt++) {
        float* op = out + (size_t)(m0 + dt) * DM + lane;
#pragma unroll
        for (int j = 0; j < 16; j++) op[32 * j] = o[dt][j];
    }
}

// ---------------------------------------------------------------------------
extern "C" void kernel_launch(void* const* d_in, const int* in_sizes, int n_in,
                              void* d_out, int out_size)
{
    const float* x      = (const float*)d_in[0];
    const float* w_qkv  = (const float*)d_in[1];
    const float* b_qkv  = (const float*)d_in[2];
    const float* w_proj = (const float*)d_in[3];
    const float* b_proj = (const float*)d_in[4];
    float* out = (float*)d_out;

    float* qkv = nullptr;
    float* att = nullptr;
    cudaGetSymbolAddress((void**)&qkv, g_qkv);
    cudaGetSymbolAddress((void**)&att, g_att);

    // 1) qkv = x @ w_qkv^T + b_qkv        [4096,1536]
    dim3 g1(QKV_N / 128, NROWS / 128);
    sgemm_nt_bias<<<g1, 256>>>(NROWS, QKV_N, DM, x, w_qkv, b_qkv, qkv);

    // 2) local windowed attention         [4096,512]
    local_attn<<<NROWS / 2 / 8, 256>>>(qkv, att);

    // 3) out = att @ w_proj^T + b_proj    [4096,512]
    dim3 g2(DM / 128, NROWS / 128);
    sgemm_nt_bias<<<g2, 256>>>(NROWS, DM, DM, att, w_proj, b_proj, out);
}

// round 2
// speedup vs baseline: 1.3534x; 1.3534x over previous
#include <cuda_runtime.h>
#include <math.h>

#define T_SEQ   2048
#define BATCH   2
#define DM      512
#define NROWS   (BATCH * T_SEQ)   // 4096
#define QKV_N   (3 * DM)          // 1536
#define WIN     32
#define WW      (2 * WIN - 1)     // 63

// Scratch (allocation-free rule: __device__ globals)
__device__ float g_qkv[NROWS * QKV_N];   // [4096, 1536] : q | k | v
__device__ float g_att[NROWS * DM];      // [4096, 512]

// ---------------------------------------------------------------------------
// C[M,N] = A[M,K] @ B[N,K]^T + bias[N].
// Double-buffered smem, vectorized LDS.128 operand fetch, one bar per k-tile.
// BN=128 fixed. BM=128 (RM=8) or BM=64 (RM=4). 256 threads, 16x16 thread grid.
// Microtile split as two 4-row groups (stride 64) x two 4-col groups
// (stride 64) -> all shared loads are conflict-free float4.
// ---------------------------------------------------------------------------
template<int BM, int RM>
__global__ __launch_bounds__(256) void sgemm_nt_bias(
    int M, int N, int K,
    const float* __restrict__ A,
    const float* __restrict__ B,
    const float* __restrict__ bias,
    float* __restrict__ C)
{
    constexpr int BN = 128, BK = 8;
    constexpr int RH = RM / 4;               // number of 4-row groups
    __shared__ float As[2][BK][BM];
    __shared__ float Bs[2][BK][BN];

    const int tid = threadIdx.x;
    const int tx  = tid & 15;                // col group selector
    const int ty  = tid >> 4;                // row group selector
    const int m0  = blockIdx.y * BM;
    const int n0  = blockIdx.x * BN;

    // global-load assignments
    int a_row, a_k;
    if (BM == 128) { a_row = tid >> 1; a_k = (tid & 1) * 4; }
    else           { a_row = tid >> 2; a_k = (tid & 3) * 2; }
    const int b_row = tid >> 1;
    const int b_k   = (tid & 1) * 4;

    const float* Ap = A + (size_t)(m0 + a_row) * K + a_k;
    const float* Bp = B + (size_t)(n0 + b_row) * K + b_k;

    float acc[RM][8];
#pragma unroll
    for (int i = 0; i < RM; i++)
#pragma unroll
        for (int j = 0; j < 8; j++) acc[i][j] = 0.0f;

    float bn[8];
#pragma unroll
    for (int g = 0; g < 2; g++)
#pragma unroll
        for (int j = 0; j < 4; j++)
            bn[g * 4 + j] = bias[n0 + g * 64 + tx * 4 + j];

    // prologue: fill buffer 0
    if (BM == 128) {
        float4 av = *reinterpret_cast<const float4*>(Ap);
        As[0][a_k + 0][a_row] = av.x;
        As[0][a_k + 1][a_row] = av.y;
        As[0][a_k + 2][a_row] = av.z;
        As[0][a_k + 3][a_row] = av.w;
    } else {
        float2 av = *reinterpret_cast<const float2*>(Ap);
        As[0][a_k + 0][a_row] = av.x;
        As[0][a_k + 1][a_row] = av.y;
    }
    {
        float4 bv = *reinterpret_cast<const float4*>(Bp);
        Bs[0][b_k + 0][b_row] = bv.x;
        Bs[0][b_k + 1][b_row] = bv.y;
        Bs[0][b_k + 2][b_row] = bv.z;
        Bs[0][b_k + 3][b_row] = bv.w;
    }
    __syncthreads();

    int buf = 0;
    for (int k0 = BK; k0 <= K; k0 += BK) {
        const bool has = (k0 < K);
        float4 av4, bv4;
        float2 av2;
        if (has) {
            if (BM == 128) av4 = *reinterpret_cast<const float4*>(Ap + k0);
            else           av2 = *reinterpret_cast<const float2*>(Ap + k0);
            bv4 = *reinterpret_cast<const float4*>(Bp + k0);
        }

#pragma unroll
        for (int k = 0; k < BK; k++) {
            float a[RM], b[8];
#pragma unroll
            for (int h = 0; h < RH; h++) {
                float4 t = *reinterpret_cast<const float4*>(&As[buf][k][h * 64 + ty * 4]);
                a[h * 4 + 0] = t.x; a[h * 4 + 1] = t.y;
                a[h * 4 + 2] = t.z; a[h * 4 + 3] = t.w;
            }
#pragma unroll
            for (int g = 0; g < 2; g++) {
                float4 t = *reinterpret_cast<const float4*>(&Bs[buf][k][g * 64 + tx * 4]);
                b[g * 4 + 0] = t.x; b[g * 4 + 1] = t.y;
                b[g * 4 + 2] = t.z; b[g * 4 + 3] = t.w;
            }
#pragma unroll
            for (int i = 0; i < RM; i++)
#pragma unroll
                for (int j = 0; j < 8; j++)
                    acc[i][j] = fmaf(a[i], b[j], acc[i][j]);
        }

        if (has) {
            const int nb = buf ^ 1;
            if (BM == 128) {
                As[nb][a_k + 0][a_row] = av4.x;
                As[nb][a_k + 1][a_row] = av4.y;
                As[nb][a_k + 2][a_row] = av4.z;
                As[nb][a_k + 3][a_row] = av4.w;
            } else {
                As[nb][a_k + 0][a_row] = av2.x;
                As[nb][a_k + 1][a_row] = av2.y;
            }
            Bs[nb][b_k + 0][b_row] = bv4.x;
            Bs[nb][b_k + 1][b_row] = bv4.y;
            Bs[nb][b_k + 2][b_row] = bv4.z;
            Bs[nb][b_k + 3][b_row] = bv4.w;
            __syncthreads();
        }
        buf ^= 1;
    }

    // epilogue
#pragma unroll
    for (int h = 0; h < RH; h++)
#pragma unroll
        for (int i = 0; i < 4; i++) {
            const int row = m0 + h * 64 + ty * 4 + i;
            float* crow = C + (size_t)row * N + n0;
#pragma unroll
            for (int g = 0; g < 2; g++) {
                float4 r;
                r.x = acc[h * 4 + i][g * 4 + 0] + bn[g * 4 + 0];
                r.y = acc[h * 4 + i][g * 4 + 1] + bn[g * 4 + 1];
                r.z = acc[h * 4 + i][g * 4 + 2] + bn[g * 4 + 2];
                r.w = acc[h * 4 + i][g * 4 + 3] + bn[g * 4 + 3];
                *reinterpret_cast<float4*>(crow + g * 64 + tx * 4) = r;
            }
        }
}

// ---------------------------------------------------------------------------
// Local windowed attention. One warp handles 2 consecutive sequence rows.
// Lane l owns channels {4l..4l+3} + 128*g (g<4): all k/v/q row reads are
// 4x LDG.128, fully coalesced. Scores live 2-per-lane.
// ---------------------------------------------------------------------------
__global__ __launch_bounds__(256) void local_attn(
    const float* __restrict__ qkv, float* __restrict__ out)
{
    const int lane = threadIdx.x & 31;
    const int wg   = (blockIdx.x * blockDim.x + threadIdx.x) >> 5;
    const int m0   = wg * 2;
    const int t0   = m0 & (T_SEQ - 1);

    const float NEG = -1e30f;
    const float inv_scale = 1.0f / 22.62741699796952f;  // 1/sqrt(512)

    // load q for both rows (4 float4s each)
    float4 q[2][4];
#pragma unroll
    for (int dt = 0; dt < 2; dt++) {
        const float* qp = qkv + (size_t)(m0 + dt) * QKV_N + lane * 4;
#pragma unroll
        for (int g = 0; g < 4; g++)
            q[dt][g] = *reinterpret_cast<const float4*>(qp + 128 * g);
    }

    float s[2][2] = {{NEG, NEG}, {NEG, NEG}};

    // ---- scores ----
    for (int d = -(WIN - 1); d <= WIN; d++) {
        const int rt = t0 + d;
        if (rt < 0 || rt >= T_SEQ) continue;
        const float* kp = qkv + (size_t)(m0 + d) * QKV_N + DM + lane * 4;
        float4 kr[4];
#pragma unroll
        for (int g = 0; g < 4; g++)
            kr[g] = *reinterpret_cast<const float4*>(kp + 128 * g);

#pragma unroll
        for (int dt = 0; dt < 2; dt++) {
            const int w = d - dt + (WIN - 1);
            if (w < 0 || w >= WW) continue;
            float dot = 0.0f;
#pragma unroll
            for (int g = 0; g < 4; g++) {
                dot = fmaf(q[dt][g].x, kr[g].x, dot);
                dot = fmaf(q[dt][g].y, kr[g].y, dot);
                dot = fmaf(q[dt][g].z, kr[g].z, dot);
                dot = fmaf(q[dt][g].w, kr[g].w, dot);
            }
#pragma unroll
            for (int o = 16; o > 0; o >>= 1)
                dot += __shfl_xor_sync(0xffffffffu, dot, o);
            if (lane == (w & 31)) s[dt][w >> 5] = dot;
        }
    }

    // ---- softmax (per row) ----
#pragma unroll
    for (int dt = 0; dt < 2; dt++) {
        float s0 = s[dt][0] * inv_scale;
        float s1 = s[dt][1] * inv_scale;
        float mx = fmaxf(s0, s1);
#pragma unroll
        for (int o = 16; o > 0; o >>= 1)
            mx = fmaxf(mx, __shfl_xor_sync(0xffffffffu, mx, o));
        float e0 = __expf(s0 - mx);
        float e1 = __expf(s1 - mx);
        float sum = e0 + e1;
#pragma unroll
        for (int o = 16; o > 0; o >>= 1)
            sum += __shfl_xor_sync(0xffffffffu, sum, o);
        float inv = 1.0f / sum;
        s[dt][0] = e0 * inv;
        s[dt][1] = e1 * inv;
    }

    // ---- output: out = p @ v_win ----
    float4 o[2][4];
#pragma unroll
    for (int dt = 0; dt < 2; dt++)
#pragma unroll
        for (int g = 0; g < 4; g++)
            o[dt][g] = make_float4(0.f, 0.f, 0.f, 0.f);

    for (int d = -(WIN - 1); d <= WIN; d++) {
        const int rt = t0 + d;
        if (rt < 0 || rt >= T_SEQ) continue;
        const float* vp = qkv + (size_t)(m0 + d) * QKV_N + 2 * DM + lane * 4;
        float4 vr[4];
#pragma unroll
        for (int g = 0; g < 4; g++)
            vr[g] = *reinterpret_cast<const float4*>(vp + 128 * g);

#pragma unroll
        for (int dt = 0; dt < 2; dt++) {
            const int w = d - dt + (WIN - 1);
            if (w < 0 || w >= WW) continue;
            const float p = __shfl_sync(0xffffffffu, s[dt][w >> 5], w & 31);
#pragma unroll
            for (int g = 0; g < 4; g++) {
                o[dt][g].x = fmaf(p, vr[g].x, o[dt][g].x);
                o[dt][g].y = fmaf(p, vr[g].y, o[dt][g].y);
                o[dt][g].z = fmaf(p, vr[g].z, o[dt][g].z);
                o[dt][g].w = fmaf(p, vr[g].w, o[dt][g].w);
            }
        }
    }

#pragma unroll
    for (int dt = 0; dt < 2; dt++) {
        float* op = out + (size_t)(m0 + dt) * DM + lane * 4;
#pragma unroll
        for (int g = 0; g < 4; g++)
            *reinterpret_cast<float4*>(op + 128 * g) = o[dt][g];
    }
}

// ---------------------------------------------------------------------------
extern "C" void kernel_launch(void* const* d_in, const int* in_sizes, int n_in,
                              void* d_out, int out_size)
{
    const float* x      = (const float*)d_in[0];
    const float* w_qkv  = (const float*)d_in[1];
    const float* b_qkv  = (const float*)d_in[2];
    const float* w_proj = (const float*)d_in[3];
    const float* b_proj = (const float*)d_in[4];
    float* out = (float*)d_out;

    float* qkv = nullptr;
    float* att = nullptr;
    cudaGetSymbolAddress((void**)&qkv, g_qkv);
    cudaGetSymbolAddress((void**)&att, g_att);

    // 1) qkv = x @ w_qkv^T + b_qkv        [4096,1536]
    dim3 g1(QKV_N / 128, NROWS / 128);
    sgemm_nt_bias<128, 8><<<g1, 256>>>(NROWS, QKV_N, DM, x, w_qkv, b_qkv, qkv);

    // 2) local windowed attention         [4096,512]
    local_attn<<<NROWS / 2 / 8, 256>>>(qkv, att);

    // 3) out = att @ w_proj^T + b_proj    [4096,512]  (BM=64 -> 256 CTAs)
    dim3 g2(DM / 128, NROWS / 64);
    sgemm_nt_bias<64, 4><<<g2, 256>>>(NROWS, DM, DM, att, w_proj, b_proj, out);
}

// round 4
// speedup vs baseline: 2.0218x; 1.4939x over previous
#include <cuda_runtime.h>
#include <cuda_bf16.h>
#include <cstdint>

#define T_SEQ   2048
#define BATCH   2
#define DM      512
#define NROWS   (BATCH * T_SEQ)   // 4096
#define QKV_N   (3 * DM)          // 1536
#define WIN     32
#define WW      (2 * WIN - 1)     // 63

// ---------------- scratch (__device__ globals: allocation-free rule) -------
__device__ float g_qkv[NROWS * QKV_N];           // fp32 q|k|v for attention
__device__ __nv_bfloat16 g_xh[NROWS * DM],  g_xl[NROWS * DM];
__device__ __nv_bfloat16 g_wqh[QKV_N * DM], g_wql[QKV_N * DM];
__device__ __nv_bfloat16 g_wph[DM * DM],    g_wpl[DM * DM];
__device__ __nv_bfloat16 g_ah[NROWS * DM],  g_al[NROWS * DM];

// ---------------- helpers ---------------------------------------------------
__device__ __forceinline__ uint32_t smem_u32(const void* p) {
    uint32_t a;
    asm("{ .reg .u64 t; cvta.to.shared.u64 t, %1; cvt.u32.u64 %0, t; }"
        : "=r"(a) : "l"(p));
    return a;
}

__device__ __forceinline__ void mma_bf16(float* c, const uint32_t* a, const uint32_t* b) {
    asm volatile(
        "mma.sync.aligned.m16n8k16.row.col.f32.bf16.bf16.f32 "
        "{%0,%1,%2,%3}, {%4,%5,%6,%7}, {%8,%9}, {%0,%1,%2,%3};"
        : "+f"(c[0]), "+f"(c[1]), "+f"(c[2]), "+f"(c[3])
        : "r"(a[0]), "r"(a[1]), "r"(a[2]), "r"(a[3]), "r"(b[0]), "r"(b[1]));
}

// smem geometry: row stride 144B (pad) -> conflict-free LDS + STS
#define ROWB   144
#define TILEB  (128 * ROWB)        // 18432 B per [128 x 64bf16] tile
#define STAGEB (4 * TILEB)         // Ah | Al | Bh | Bl
#define GEMM_SMEM (2 * STAGEB)     // 147456 B double buffered

// ---------------------------------------------------------------------------
// fp32 -> (hi, lo) bf16 split
// ---------------------------------------------------------------------------
__global__ __launch_bounds__(256) void split_bf16(
    const float4* __restrict__ src,
    __nv_bfloat16* __restrict__ hi, __nv_bfloat16* __restrict__ lo, int n4)
{
    int i = blockIdx.x * blockDim.x + threadIdx.x;
    if (i >= n4) return;
    float4 v = src[i];
    float xs[4] = {v.x, v.y, v.z, v.w};
    unsigned short h[4], l[4];
#pragma unroll
    for (int j = 0; j < 4; j++) {
        __nv_bfloat16 hb = __float2bfloat16(xs[j]);
        __nv_bfloat16 lb = __float2bfloat16(xs[j] - __bfloat162float(hb));
        h[j] = __bfloat16_as_ushort(hb);
        l[j] = __bfloat16_as_ushort(lb);
    }
    uint2 hv, lv;
    hv.x = h[0] | ((uint32_t)h[1] << 16);
    hv.y = h[2] | ((uint32_t)h[3] << 16);
    lv.x = l[0] | ((uint32_t)l[1] << 16);
    lv.y = l[2] | ((uint32_t)l[3] << 16);
    reinterpret_cast<uint2*>(hi)[i] = hv;
    reinterpret_cast<uint2*>(lo)[i] = lv;
}

// ---------------------------------------------------------------------------
// Split-bf16 HMMA GEMM: C[M,Ntot] = A[M,K] @ B[Ntot,K]^T + bias
// D = Ah*Bh + Ah*Bl + Al*Bh  (fp32 accumulate).
// CTA 128x128, 8 warps x (64x32), K staged 64-wide, cp.async double buffer.
// ---------------------------------------------------------------------------
__global__ __launch_bounds__(256) void gemm_split_mma(
    int Ntot, int kchunks,
    const __nv_bfloat16* __restrict__ Ah, const __nv_bfloat16* __restrict__ Al,
    const __nv_bfloat16* __restrict__ Bh, const __nv_bfloat16* __restrict__ Bl,
    const float* __restrict__ bias, float* __restrict__ C)
{
    extern __shared__ __align__(16) char smem[];
    const uint32_t sbase = smem_u32(smem);

    const int tid    = threadIdx.x;
    const int wid    = tid >> 5;
    const int lane   = tid & 31;
    const int l4     = lane >> 2;      // 0..7
    const int lq     = lane & 3;       // 0..3
    const int warp_m = (wid & 1) * 64;
    const int warp_n = (wid >> 1) * 32;
    const int m0     = blockIdx.y * 128;
    const int n0     = blockIdx.x * 128;
    const int K      = kchunks * 64;

    const __nv_bfloat16* srcs[4] = {Ah, Al, Bh, Bl};

    // ---- async stage loader: 4 tiles of [128 x 64bf16] ----
    const int ld_row  = tid >> 1;
    const int ld_half = tid & 1;
    auto issue_stage = [&](int c, int buf) {
#pragma unroll
        for (int t = 0; t < 4; t++) {
            const int rbase = (t < 2) ? m0 : n0;
            const __nv_bfloat16* gp =
                srcs[t] + (size_t)(rbase + ld_row) * K + c * 64 + ld_half * 32;
            const uint32_t sa = sbase + buf * STAGEB + t * TILEB
                              + ld_row * ROWB + ld_half * 64;
#pragma unroll
            for (int j = 0; j < 4; j++)
                asm volatile("cp.async.cg.shared.global [%0], [%1], 16;"
                             :: "r"(sa + j * 16), "l"(gp + j * 8) : "memory");
        }
        asm volatile("cp.async.commit_group;" ::: "memory");
    };

    float acc[4][4][4];
#pragma unroll
    for (int i = 0; i < 4; i++)
#pragma unroll
        for (int j = 0; j < 4; j++)
#pragma unroll
            for (int r = 0; r < 4; r++) acc[i][j][r] = 0.0f;

    issue_stage(0, 0);
    if (kchunks > 1) issue_stage(1, 1);

    for (int c = 0; c < kchunks; c++) {
        const int buf = c & 1;
        if (c + 1 < kchunks) asm volatile("cp.async.wait_group 1;" ::: "memory");
        else                 asm volatile("cp.async.wait_group 0;" ::: "memory");
        __syncthreads();

        const char* Abh = smem + buf * STAGEB;             // Ah tile
        const char* Abl = Abh + TILEB;                     // Al tile
        const char* Bbh = Abh + 2 * TILEB;                 // Bh tile
        const char* Bbl = Abh + 3 * TILEB;                 // Bl tile

#pragma unroll
        for (int kk = 0; kk < 4; kk++) {
            uint32_t ah[4][4], al[4][4];
#pragma unroll
            for (int mt = 0; mt < 4; mt++) {
#pragma unroll
                for (int r = 0; r < 4; r++) {
                    const int row = warp_m + mt * 16 + l4 + (r & 1) * 8;
                    const int kof = kk * 16 + 2 * lq + (r >> 1) * 8;
                    ah[mt][r] = *reinterpret_cast<const uint32_t*>(
                        Abh + row * ROWB + kof * 2);
                    al[mt][r] = *reinterpret_cast<const uint32_t*>(
                        Abl + row * ROWB + kof * 2);
                }
            }
#pragma unroll
            for (int nt = 0; nt < 4; nt++) {
                uint32_t bh[2], bl[2];
#pragma unroll
                for (int r = 0; r < 2; r++) {
                    const int row = warp_n + nt * 8 + l4;
                    const int kof = kk * 16 + 2 * lq + r * 8;
                    bh[r] = *reinterpret_cast<const uint32_t*>(
                        Bbh + row * ROWB + kof * 2);
                    bl[r] = *reinterpret_cast<const uint32_t*>(
                        Bbl + row * ROWB + kof * 2);
                }
#pragma unroll
                for (int mt = 0; mt < 4; mt++) {
                    mma_bf16(acc[mt][nt], ah[mt], bh);
                    mma_bf16(acc[mt][nt], ah[mt], bl);
                    mma_bf16(acc[mt][nt], al[mt], bh);
                }
            }
        }

        __syncthreads();
        if (c + 2 < kchunks) issue_stage(c + 2, buf);
    }

    // ---- epilogue: fp32 + bias ----
#pragma unroll
    for (int nt = 0; nt < 4; nt++) {
        const int col = n0 + warp_n + nt * 8 + 2 * lq;
        const float2 bv = *reinterpret_cast<const float2*>(bias + col);
#pragma unroll
        for (int mt = 0; mt < 4; mt++) {
            const int row = m0 + warp_m + mt * 16 + l4;
            float2 r0, r1;
            r0.x = acc[mt][nt][0] + bv.x;
            r0.y = acc[mt][nt][1] + bv.y;
            r1.x = acc[mt][nt][2] + bv.x;
            r1.y = acc[mt][nt][3] + bv.y;
            *reinterpret_cast<float2*>(C + (size_t)row * Ntot + col) = r0;
            *reinterpret_cast<float2*>(C + (size_t)(row + 8) * Ntot + col) = r1;
        }
    }
}

// ---------------------------------------------------------------------------
// Local windowed attention: 1 warp = 2 rows; emits hi/lo bf16 split directly.
// ---------------------------------------------------------------------------
__global__ __launch_bounds__(256) void local_attn(
    const float* __restrict__ qkv,
    __nv_bfloat16* __restrict__ oh, __nv_bfloat16* __restrict__ ol)
{
    const int lane = threadIdx.x & 31;
    const int wg   = (blockIdx.x * blockDim.x + threadIdx.x) >> 5;
    const int m0   = wg * 2;
    const int t0   = m0 & (T_SEQ - 1);

    const float NEG = -1e30f;
    const float inv_scale = 1.0f / 22.62741699796952f;  // 1/sqrt(512)

    float4 q[2][4];
#pragma unroll
    for (int dt = 0; dt < 2; dt++) {
        const float* qp = qkv + (size_t)(m0 + dt) * QKV_N + lane * 4;
#pragma unroll
        for (int g = 0; g < 4; g++)
            q[dt][g] = *reinterpret_cast<const float4*>(qp + 128 * g);
    }

    float s[2][2] = {{NEG, NEG}, {NEG, NEG}};

    for (int d = -(WIN - 1); d <= WIN; d++) {
        const int rt = t0 + d;
        if (rt < 0 || rt >= T_SEQ) continue;
        const float* kp = qkv + (size_t)(m0 + d) * QKV_N + DM + lane * 4;
        float4 kr[4];
#pragma unroll
        for (int g = 0; g < 4; g++)
            kr[g] = *reinterpret_cast<const float4*>(kp + 128 * g);

#pragma unroll
        for (int dt = 0; dt < 2; dt++) {
            const int w = d - dt + (WIN - 1);
            if (w < 0 || w >= WW) continue;
            float dot = 0.0f;
#pragma unroll
            for (int g = 0; g < 4; g++) {
                dot = fmaf(q[dt][g].x, kr[g].x, dot);
                dot = fmaf(q[dt][g].y, kr[g].y, dot);
                dot = fmaf(q[dt][g].z, kr[g].z, dot);
                dot = fmaf(q[dt][g].w, kr[g].w, dot);
            }
#pragma unroll
            for (int o = 16; o > 0; o >>= 1)
                dot += __shfl_xor_sync(0xffffffffu, dot, o);
            if (lane == (w & 31)) s[dt][w >> 5] = dot;
        }
    }

#pragma unroll
    for (int dt = 0; dt < 2; dt++) {
        float s0 = s[dt][0] * inv_scale;
        float s1 = s[dt][1] * inv_scale;
        float mx = fmaxf(s0, s1);
#pragma unroll
        for (int o = 16; o > 0; o >>= 1)
            mx = fmaxf(mx, __shfl_xor_sync(0xffffffffu, mx, o));
        float e0 = __expf(s0 - mx);
        float e1 = __expf(s1 - mx);
        float sum = e0 + e1;
#pragma unroll
        for (int o = 16; o > 0; o >>= 1)
            sum += __shfl_xor_sync(0xffffffffu, sum, o);
        float inv = 1.0f / sum;
        s[dt][0] = e0 * inv;
        s[dt][1] = e1 * inv;
    }

    float4 o[2][4];
#pragma unroll
    for (int dt = 0; dt < 2; dt++)
#pragma unroll
        for (int g = 0; g < 4; g++)
            o[dt][g] = make_float4(0.f, 0.f, 0.f, 0.f);

    for (int d = -(WIN - 1); d <= WIN; d++) {
        const int rt = t0 + d;
        if (rt < 0 || rt >= T_SEQ) continue;
        const float* vp = qkv + (size_t)(m0 + d) * QKV_N + 2 * DM + lane * 4;
        float4 vr[4];
#pragma unroll
        for (int g = 0; g < 4; g++)
            vr[g] = *reinterpret_cast<const float4*>(vp + 128 * g);

#pragma unroll
        for (int dt = 0; dt < 2; dt++) {
            const int w = d - dt + (WIN - 1);
            if (w < 0 || w >= WW) continue;
            const float p = __shfl_sync(0xffffffffu, s[dt][w >> 5], w & 31);
#pragma unroll
            for (int g = 0; g < 4; g++) {
                o[dt][g].x = fmaf(p, vr[g].x, o[dt][g].x);
                o[dt][g].y = fmaf(p, vr[g].y, o[dt][g].y);
                o[dt][g].z = fmaf(p, vr[g].z, o[dt][g].z);
                o[dt][g].w = fmaf(p, vr[g].w, o[dt][g].w);
            }
        }
    }

    // write hi/lo bf16 split directly
#pragma unroll
    for (int dt = 0; dt < 2; dt++) {
        const size_t base = (size_t)(m0 + dt) * DM + lane * 4;
#pragma unroll
        for (int g = 0; g < 4; g++) {
            float vals[4] = {o[dt][g].x, o[dt][g].y, o[dt][g].z, o[dt][g].w};
            unsigned short h[4], l[4];
#pragma unroll
            for (int j = 0; j < 4; j++) {
                __nv_bfloat16 hb = __float2bfloat16(vals[j]);
                __nv_bfloat16 lb = __float2bfloat16(vals[j] - __bfloat162float(hb));
                h[j] = __bfloat16_as_ushort(hb);
                l[j] = __bfloat16_as_ushort(lb);
            }
            uint2 hv, lv;
            hv.x = h[0] | ((uint32_t)h[1] << 16);
            hv.y = h[2] | ((uint32_t)h[3] << 16);
            lv.x = l[0] | ((uint32_t)l[1] << 16);
            lv.y = l[2] | ((uint32_t)l[3] << 16);
            *reinterpret_cast<uint2*>(oh + base + 128 * g) = hv;
            *reinterpret_cast<uint2*>(ol + base + 128 * g) = lv;
        }
    }
}

// ---------------------------------------------------------------------------
extern "C" void kernel_launch(void* const* d_in, const int* in_sizes, int n_in,
                              void* d_out, int out_size)
{
    const float* x      = (const float*)d_in[0];
    const float* w_qkv  = (const float*)d_in[1];
    const float* b_qkv  = (const float*)d_in[2];
    const float* w_proj = (const float*)d_in[3];
    const float* b_proj = (const float*)d_in[4];
    float* out = (float*)d_out;

    float* qkv;
    __nv_bfloat16 *xh, *xl, *wqh, *wql, *wph, *wpl, *ah, *al;
    cudaGetSymbolAddress((void**)&qkv, g_qkv);
    cudaGetSymbolAddress((void**)&xh,  g_xh);
    cudaGetSymbolAddress((void**)&xl,  g_xl);
    cudaGetSymbolAddress((void**)&wqh, g_wqh);
    cudaGetSymbolAddress((void**)&wql, g_wql);
    cudaGetSymbolAddress((void**)&wph, g_wph);
    cudaGetSymbolAddress((void**)&wpl, g_wpl);
    cudaGetSymbolAddress((void**)&ah,  g_ah);
    cudaGetSymbolAddress((void**)&al,  g_al);

    static bool attr_set = false;
    if (!attr_set) {
        cudaFuncSetAttribute(gemm_split_mma,
                             cudaFuncAttributeMaxDynamicSharedMemorySize, GEMM_SMEM);
        attr_set = true;
    }

    // 0) precision splits
    split_bf16<<<(NROWS * DM / 4 + 255) / 256, 256>>>((const float4*)x, xh, xl, NROWS * DM / 4);
    split_bf16<<<(QKV_N * DM / 4 + 255) / 256, 256>>>((const float4*)w_qkv, wqh, wql, QKV_N * DM / 4);
    split_bf16<<<(DM * DM / 4 + 255) / 256, 256>>>((const float4*)w_proj, wph, wpl, DM * DM / 4);

    // 1) qkv = x @ w_qkv^T + b_qkv   [4096,1536]  (HMMA split-bf16)
    gemm_split_mma<<<dim3(QKV_N / 128, NROWS / 128), 256, GEMM_SMEM>>>(
        QKV_N, DM / 64, xh, xl, wqh, wql, b_qkv, qkv);

    // 2) local windowed attention -> hi/lo bf16 [4096,512]
    local_attn<<<NROWS / 2 / 8, 256>>>(qkv, ah, al);

    // 3) out = att @ w_proj^T + b_proj
    gemm_split_mma<<<dim3(DM / 128, NROWS / 128), 256, GEMM_SMEM>>>(
        DM, DM / 64, ah, al, wph, wpl, b_proj, out);
}

// round 5
// speedup vs baseline: 2.1150x; 1.0461x over previous
#include <cuda_runtime.h>
#include <cuda_bf16.h>
#include <cstdint>

#define T_SEQ   2048
#define BATCH   2
#define DM      512
#define NROWS   (BATCH * T_SEQ)   // 4096
#define QKV_N   (3 * DM)          // 1536
#define WIN     32
#define WW      (2 * WIN - 1)     // 63

// ---------------- scratch (__device__ globals: allocation-free rule) -------
__device__ float g_qkv[NROWS * QKV_N];           // fp32 q|k|v for attention
__device__ __nv_bfloat16 g_xh[NROWS * DM],  g_xl[NROWS * DM];
__device__ __nv_bfloat16 g_wqh[QKV_N * DM], g_wql[QKV_N * DM];
__device__ __nv_bfloat16 g_wph[DM * DM],    g_wpl[DM * DM];
__device__ __nv_bfloat16 g_ah[NROWS * DM],  g_al[NROWS * DM];

// ---------------- helpers ---------------------------------------------------
__device__ __forceinline__ uint32_t smem_u32(const void* p) {
    uint32_t a;
    asm("{ .reg .u64 t; cvta.to.shared.u64 t, %1; cvt.u32.u64 %0, t; }"
        : "=r"(a) : "l"(p));
    return a;
}

__device__ __forceinline__ void mma_bf16(float* c, const uint32_t* a, const uint32_t* b) {
    asm volatile(
        "mma.sync.aligned.m16n8k16.row.col.f32.bf16.bf16.f32 "
        "{%0,%1,%2,%3}, {%4,%5,%6,%7}, {%8,%9}, {%0,%1,%2,%3};"
        : "+f"(c[0]), "+f"(c[1]), "+f"(c[2]), "+f"(c[3])
        : "r"(a[0]), "r"(a[1]), "r"(a[2]), "r"(a[3]), "r"(b[0]), "r"(b[1]));
}

__device__ __forceinline__ void ldm_x4(uint32_t* d, uint32_t addr) {
    asm volatile("ldmatrix.sync.aligned.m8n8.x4.shared.b16 {%0,%1,%2,%3}, [%4];"
                 : "=r"(d[0]), "=r"(d[1]), "=r"(d[2]), "=r"(d[3]) : "r"(addr));
}
__device__ __forceinline__ void ldm_x2(uint32_t* d, uint32_t addr) {
    asm volatile("ldmatrix.sync.aligned.m8n8.x2.shared.b16 {%0,%1}, [%2];"
                 : "=r"(d[0]), "=r"(d[1]) : "r"(addr));
}

// smem geometry: K-chunk 32 bf16 (64B) + 16B pad -> 80B row stride.
// Bank check: stride 20 words; l4*20 mod 32 = {0,20,8,28,16,4,24,12}; +lq(0..3)
// covers all 32 banks -> conflict-free for ldmatrix & cp.async.
#define ROWB   80
#define TILEB  (128 * ROWB)        // 10240 B per [128 x 32bf16] tile
#define STAGEB (4 * TILEB)         // Ah | Al | Bh | Bl = 40960 B
#define GEMM_SMEM (2 * STAGEB)     // 81920 B double buffered -> 2 CTAs/SM

// ---------------------------------------------------------------------------
// fp32 -> (hi, lo) bf16 split
// ---------------------------------------------------------------------------
__global__ __launch_bounds__(256) void split_bf16(
    const float4* __restrict__ src,
    __nv_bfloat16* __restrict__ hi, __nv_bfloat16* __restrict__ lo, int n4)
{
    int i = blockIdx.x * blockDim.x + threadIdx.x;
    if (i >= n4) return;
    float4 v = src[i];
    float xs[4] = {v.x, v.y, v.z, v.w};
    unsigned short h[4], l[4];
#pragma unroll
    for (int j = 0; j < 4; j++) {
        __nv_bfloat16 hb = __float2bfloat16(xs[j]);
        __nv_bfloat16 lb = __float2bfloat16(xs[j] - __bfloat162float(hb));
        h[j] = __bfloat16_as_ushort(hb);
        l[j] = __bfloat16_as_ushort(lb);
    }
    uint2 hv, lv;
    hv.x = h[0] | ((uint32_t)h[1] << 16);
    hv.y = h[2] | ((uint32_t)h[3] << 16);
    lv.x = l[0] | ((uint32_t)l[1] << 16);
    lv.y = l[2] | ((uint32_t)l[3] << 16);
    reinterpret_cast<uint2*>(hi)[i] = hv;
    reinterpret_cast<uint2*>(lo)[i] = lv;
}

// ---------------------------------------------------------------------------
// Split-bf16 HMMA GEMM: C[M,Ntot] = A[M,K] @ B[Ntot,K]^T + bias
// D = Ah*Bh + Ah*Bl + Al*Bh (fp32 accum). CTA 128x128, 8 warps x (64x32).
// K chunk 32, double-buffered cp.async, ldmatrix fragment loads, 2 CTAs/SM.
// ---------------------------------------------------------------------------
__global__ __launch_bounds__(256, 2) void gemm_split_mma(
    int Ntot, int kchunks,
    const __nv_bfloat16* __restrict__ Ah, const __nv_bfloat16* __restrict__ Al,
    const __nv_bfloat16* __restrict__ Bh, const __nv_bfloat16* __restrict__ Bl,
    const float* __restrict__ bias, float* __restrict__ C)
{
    extern __shared__ __align__(16) char smem[];
    const uint32_t sbase = smem_u32(smem);

    const int tid    = threadIdx.x;
    const int wid    = tid >> 5;
    const int lane   = tid & 31;
    const int l4     = lane >> 2;
    const int lq     = lane & 3;
    const int warp_m = (wid & 1) * 64;
    const int warp_n = (wid >> 1) * 32;
    const int m0     = blockIdx.y * 128;
    const int n0     = blockIdx.x * 128;
    const int K      = kchunks * 32;

    const __nv_bfloat16* srcs[4] = {Ah, Al, Bh, Bl};

    // per-lane ldmatrix source offsets (within a tile)
    const int g8  = lane >> 3;          // 0..3
    const int r8  = lane & 7;           // 0..7
    // A x4: matrices (m0-7,k0),(m8-15,k0),(m0-7,k8),(m8-15,k8)
    const uint32_t a_off = (uint32_t)((warp_m + (g8 & 1) * 8 + r8) * ROWB + (g8 >> 1) * 16);
    // B x2: matrices (n0-7,k0),(n0-7,k8)  (lanes 0-15 supply addresses)
    const uint32_t b_off = (uint32_t)((warp_n + r8) * ROWB + ((lane >> 3) & 1) * 16);

    // ---- async stage loader: 4 tiles of [128 x 32bf16] ----
    const int ld_row  = tid >> 1;
    const int ld_half = tid & 1;
    auto issue_stage = [&](int c, int buf) {
#pragma unroll
        for (int t = 0; t < 4; t++) {
            const int rbase = (t < 2) ? m0 : n0;
            const __nv_bfloat16* gp =
                srcs[t] + (size_t)(rbase + ld_row) * K + c * 32 + ld_half * 16;
            const uint32_t sa = sbase + buf * STAGEB + t * TILEB
                              + ld_row * ROWB + ld_half * 32;
#pragma unroll
            for (int j = 0; j < 2; j++)
                asm volatile("cp.async.cg.shared.global [%0], [%1], 16;"
                             :: "r"(sa + j * 16), "l"(gp + j * 8) : "memory");
        }
        asm volatile("cp.async.commit_group;" ::: "memory");
    };

    float acc[4][4][4];
#pragma unroll
    for (int i = 0; i < 4; i++)
#pragma unroll
        for (int j = 0; j < 4; j++)
#pragma unroll
            for (int r = 0; r < 4; r++) acc[i][j][r] = 0.0f;

    issue_stage(0, 0);
    if (kchunks > 1) issue_stage(1, 1);

    for (int c = 0; c < kchunks; c++) {
        const int buf = c & 1;
        if (c + 1 < kchunks) asm volatile("cp.async.wait_group 1;" ::: "memory");
        else                 asm volatile("cp.async.wait_group 0;" ::: "memory");
        __syncthreads();

        const uint32_t stage = sbase + buf * STAGEB;
        const uint32_t Abh = stage;
        const uint32_t Abl = stage + TILEB;
        const uint32_t Bbh = stage + 2 * TILEB;
        const uint32_t Bbl = stage + 3 * TILEB;

#pragma unroll
        for (int kk = 0; kk < 2; kk++) {
            uint32_t ah[4][4], al[4][4];
#pragma unroll
            for (int mt = 0; mt < 4; mt++) {
                const uint32_t o = a_off + mt * 16 * ROWB + kk * 32;
                ldm_x4(ah[mt], Abh + o);
                ldm_x4(al[mt], Abl + o);
            }
#pragma unroll
            for (int nt = 0; nt < 4; nt++) {
                const uint32_t o = b_off + nt * 8 * ROWB + kk * 32;
                uint32_t bh[2], bl[2];
                ldm_x2(bh, Bbh + o);
                ldm_x2(bl, Bbl + o);
#pragma unroll
                for (int mt = 0; mt < 4; mt++) {
                    mma_bf16(acc[mt][nt], ah[mt], bh);
                    mma_bf16(acc[mt][nt], ah[mt], bl);
                    mma_bf16(acc[mt][nt], al[mt], bh);
                }
            }
        }

        __syncthreads();
        if (c + 2 < kchunks) issue_stage(c + 2, buf);
    }

    // ---- epilogue: fp32 + bias ----
#pragma unroll
    for (int nt = 0; nt < 4; nt++) {
        const int col = n0 + warp_n + nt * 8 + 2 * lq;
        const float2 bv = *reinterpret_cast<const float2*>(bias + col);
#pragma unroll
        for (int mt = 0; mt < 4; mt++) {
            const int row = m0 + warp_m + mt * 16 + l4;
            float2 r0, r1;
            r0.x = acc[mt][nt][0] + bv.x;
            r0.y = acc[mt][nt][1] + bv.y;
            r1.x = acc[mt][nt][2] + bv.x;
            r1.y = acc[mt][nt][3] + bv.y;
            *reinterpret_cast<float2*>(C + (size_t)row * Ntot + col) = r0;
            *reinterpret_cast<float2*>(C + (size_t)(row + 8) * Ntot + col) = r1;
        }
    }
}

// ---------------------------------------------------------------------------
// Local windowed attention: 1 warp = 2 rows; emits hi/lo bf16 split directly.
// ---------------------------------------------------------------------------
__global__ __launch_bounds__(256) void local_attn(
    const float* __restrict__ qkv,
    __nv_bfloat16* __restrict__ oh, __nv_bfloat16* __restrict__ ol)
{
    const int lane = threadIdx.x & 31;
    const int wg   = (blockIdx.x * blockDim.x + threadIdx.x) >> 5;
    const int m0   = wg * 2;
    const int t0   = m0 & (T_SEQ - 1);

    const float NEG = -1e30f;
    const float inv_scale = 1.0f / 22.62741699796952f;  // 1/sqrt(512)

    float4 q[2][4];
#pragma unroll
    for (int dt = 0; dt < 2; dt++) {
        const float* qp = qkv + (size_t)(m0 + dt) * QKV_N + lane * 4;
#pragma unroll
        for (int g = 0; g < 4; g++)
            q[dt][g] = *reinterpret_cast<const float4*>(qp + 128 * g);
    }

    float s[2][2] = {{NEG, NEG}, {NEG, NEG}};

    for (int d = -(WIN - 1); d <= WIN; d++) {
        const int rt = t0 + d;
        if (rt < 0 || rt >= T_SEQ) continue;
        const float* kp = qkv + (size_t)(m0 + d) * QKV_N + DM + lane * 4;
        float4 kr[4];
#pragma unroll
        for (int g = 0; g < 4; g++)
            kr[g] = *reinterpret_cast<const float4*>(kp + 128 * g);

#pragma unroll
        for (int dt = 0; dt < 2; dt++) {
            const int w = d - dt + (WIN - 1);
            if (w < 0 || w >= WW) continue;
            float dot = 0.0f;
#pragma unroll
            for (int g = 0; g < 4; g++) {
                dot = fmaf(q[dt][g].x, kr[g].x, dot);
                dot = fmaf(q[dt][g].y, kr[g].y, dot);
                dot = fmaf(q[dt][g].z, kr[g].z, dot);
                dot = fmaf(q[dt][g].w, kr[g].w, dot);
            }
#pragma unroll
            for (int o = 16; o > 0; o >>= 1)
                dot += __shfl_xor_sync(0xffffffffu, dot, o);
            if (lane == (w & 31)) s[dt][w >> 5] = dot;
        }
    }

#pragma unroll
    for (int dt = 0; dt < 2; dt++) {
        float s0 = s[dt][0] * inv_scale;
        float s1 = s[dt][1] * inv_scale;
        float mx = fmaxf(s0, s1);
#pragma unroll
        for (int o = 16; o > 0; o >>= 1)
            mx = fmaxf(mx, __shfl_xor_sync(0xffffffffu, mx, o));
        float e0 = __expf(s0 - mx);
        float e1 = __expf(s1 - mx);
        float sum = e0 + e1;
#pragma unroll
        for (int o = 16; o > 0; o >>= 1)
            sum += __shfl_xor_sync(0xffffffffu, sum, o);
        float inv = 1.0f / sum;
        s[dt][0] = e0 * inv;
        s[dt][1] = e1 * inv;
    }

    float4 o[2][4];
#pragma unroll
    for (int dt = 0; dt < 2; dt++)
#pragma unroll
        for (int g = 0; g < 4; g++)
            o[dt][g] = make_float4(0.f, 0.f, 0.f, 0.f);

    for (int d = -(WIN - 1); d <= WIN; d++) {
        const int rt = t0 + d;
        if (rt < 0 || rt >= T_SEQ) continue;
        const float* vp = qkv + (size_t)(m0 + d) * QKV_N + 2 * DM + lane * 4;
        float4 vr[4];
#pragma unroll
        for (int g = 0; g < 4; g++)
            vr[g] = *reinterpret_cast<const float4*>(vp + 128 * g);

#pragma unroll
        for (int dt = 0; dt < 2; dt++) {
            const int w = d - dt + (WIN - 1);
            if (w < 0 || w >= WW) continue;
            const float p = __shfl_sync(0xffffffffu, s[dt][w >> 5], w & 31);
#pragma unroll
            for (int g = 0; g < 4; g++) {
                o[dt][g].x = fmaf(p, vr[g].x, o[dt][g].x);
                o[dt][g].y = fmaf(p, vr[g].y, o[dt][g].y);
                o[dt][g].z = fmaf(p, vr[g].z, o[dt][g].z);
                o[dt][g].w = fmaf(p, vr[g].w, o[dt][g].w);
            }
        }
    }

    // write hi/lo bf16 split directly
#pragma unroll
    for (int dt = 0; dt < 2; dt++) {
        const size_t base = (size_t)(m0 + dt) * DM + lane * 4;
#pragma unroll
        for (int g = 0; g < 4; g++) {
            float vals[4] = {o[dt][g].x, o[dt][g].y, o[dt][g].z, o[dt][g].w};
            unsigned short h[4], l[4];
#pragma unroll
            for (int j = 0; j < 4; j++) {
                __nv_bfloat16 hb = __float2bfloat16(vals[j]);
                __nv_bfloat16 lb = __float2bfloat16(vals[j] - __bfloat162float(hb));
                h[j] = __bfloat16_as_ushort(hb);
                l[j] = __bfloat16_as_ushort(lb);
            }
            uint2 hv, lv;
            hv.x = h[0] | ((uint32_t)h[1] << 16);
            hv.y = h[2] | ((uint32_t)h[3] << 16);
            lv.x = l[0] | ((uint32_t)l[1] << 16);
            lv.y = l[2] | ((uint32_t)l[3] << 16);
            *reinterpret_cast<uint2*>(oh + base + 128 * g) = hv;
            *reinterpret_cast<uint2*>(ol + base + 128 * g) = lv;
        }
    }
}

// ---------------------------------------------------------------------------
extern "C" void kernel_launch(void* const* d_in, const int* in_sizes, int n_in,
                              void* d_out, int out_size)
{
    const float* x      = (const float*)d_in[0];
    const float* w_qkv  = (const float*)d_in[1];
    const float* b_qkv  = (const float*)d_in[2];
    const float* w_proj = (const float*)d_in[3];
    const float* b_proj = (const float*)d_in[4];
    float* out = (float*)d_out;

    float* qkv;
    __nv_bfloat16 *xh, *xl, *wqh, *wql, *wph, *wpl, *ah, *al;
    cudaGetSymbolAddress((void**)&qkv, g_qkv);
    cudaGetSymbolAddress((void**)&xh,  g_xh);
    cudaGetSymbolAddress((void**)&xl,  g_xl);
    cudaGetSymbolAddress((void**)&wqh, g_wqh);
    cudaGetSymbolAddress((void**)&wql, g_wql);
    cudaGetSymbolAddress((void**)&wph, g_wph);
    cudaGetSymbolAddress((void**)&wpl, g_wpl);
    cudaGetSymbolAddress((void**)&ah,  g_ah);
    cudaGetSymbolAddress((void**)&al,  g_al);

    static bool attr_set = false;
    if (!attr_set) {
        cudaFuncSetAttribute(gemm_split_mma,
                             cudaFuncAttributeMaxDynamicSharedMemorySize, GEMM_SMEM);
        attr_set = true;
    }

    // 0) precision splits
    split_bf16<<<(NROWS * DM / 4 + 255) / 256, 256>>>((const float4*)x, xh, xl, NROWS * DM / 4);
    split_bf16<<<(QKV_N * DM / 4 + 255) / 256, 256>>>((const float4*)w_qkv, wqh, wql, QKV_N * DM / 4);
    split_bf16<<<(DM * DM / 4 + 255) / 256, 256>>>((const float4*)w_proj, wph, wpl, DM * DM / 4);

    // 1) qkv = x @ w_qkv^T + b_qkv   [4096,1536]  (HMMA split-bf16)
    gemm_split_mma<<<dim3(QKV_N / 128, NROWS / 128), 256, GEMM_SMEM>>>(
        QKV_N, DM / 32, xh, xl, wqh, wql, b_qkv, qkv);

    // 2) local windowed attention -> hi/lo bf16 [4096,512]
    local_attn<<<NROWS / 2 / 8, 256>>>(qkv, ah, al);

    // 3) out = att @ w_proj^T + b_proj
    gemm_split_mma<<<dim3(DM / 128, NROWS / 128), 256, GEMM_SMEM>>>(
        DM, DM / 32, ah, al, wph, wpl, b_proj, out);
}